// round 1
// baseline (speedup 1.0000x reference)
#include <cuda_runtime.h>
#include <cuda_bf16.h>

// Problem constants (fixed by the dataset):
//   N = 55440*1024 = 56,770,560 fp32 elements
//   Candidate lengths: L in [4,32], N % L == 0  -> 20 candidates
//   P = lcm(candidates) = 110880, N / P = 512
#define NTOT   56770560
#define PP     110880
#define PP4    27720        // PP / 4 (float4 positions)
#define RSPLIT 4            // split the 512 repeats 4 ways for occupancy
#define RCHUNK 128          // 512 / RSPLIT
#define NCAND  20

// Scratch (allocation-free rule: __device__ globals)
__device__ float4   g_pmn4[RSPLIT * PP4];   // partial per-position min
__device__ float4   g_pmx4[RSPLIT * PP4];   // partial per-position max
__device__ unsigned g_md[NCAND];            // float-bit max per candidate

// ---------------------------------------------------------------------------
// Stage 0: zero the atomicMax targets (diffs >= 0, bits(0.0f) == 0)
// ---------------------------------------------------------------------------
__global__ void pm_init() {
    if (threadIdx.x < NCAND) g_md[threadIdx.x] = 0u;
}

// ---------------------------------------------------------------------------
// Stage 1: per-period-position min/max over one r-chunk of 128 repeats.
// Thread t (of PP4) handles 4 consecutive positions via float4; blockIdx.y
// selects the r-chunk. Warp loads are 512B contiguous -> fully coalesced.
// ---------------------------------------------------------------------------
__global__ __launch_bounds__(256) void pm_stage1(const float4* __restrict__ x4) {
    int t = blockIdx.x * blockDim.x + threadIdx.x;
    if (t >= PP4) return;
    int c = blockIdx.y;

    int base = c * (RCHUNK * PP4) + t;
    float4 v = x4[base];
    float4 mn = v, mx = v;

#pragma unroll 8
    for (int r = 1; r < RCHUNK; r++) {
        float4 u = x4[base + r * PP4];
        mn.x = fminf(mn.x, u.x); mx.x = fmaxf(mx.x, u.x);
        mn.y = fminf(mn.y, u.y); mx.y = fmaxf(mx.y, u.y);
        mn.z = fminf(mn.z, u.z); mx.z = fmaxf(mx.z, u.z);
        mn.w = fminf(mn.w, u.w); mx.w = fmaxf(mx.w, u.w);
    }
    g_pmn4[c * PP4 + t] = mn;
    g_pmx4[c * PP4 + t] = mx;
}

// ---------------------------------------------------------------------------
// Stage 2: combine the 4 partials and, for every period position p, fold
// max(mx[p]-pat, pat-mn[p]) into the per-L accumulators. pat = x[p % L],
// with p % L a compile-time-constant modulus (unrolled) -> mul/shift.
// Exactness: max_v |fl(v-c)| = max(fl(mx-c), fl(c-mn)) since fl is monotone
// and sign-symmetric, and the max of |v-c| over a set is at an extreme.
// ---------------------------------------------------------------------------
__global__ __launch_bounds__(256) void pm_stage2(const float* __restrict__ x) {
    __shared__ float    s_pat[32];
    __shared__ unsigned s_max[NCAND];
    if (threadIdx.x < 32)     s_pat[threadIdx.x] = x[threadIdx.x];
    if (threadIdx.x < NCAND)  s_max[threadIdx.x] = 0u;
    __syncthreads();

    const int LENS[NCAND] = {4,5,6,7,8,9,10,11,12,14,15,16,18,20,21,22,24,28,30,32};

    float acc[NCAND];
#pragma unroll
    for (int k = 0; k < NCAND; k++) acc[k] = 0.0f;

    for (int t = blockIdx.x * blockDim.x + threadIdx.x; t < PP4;
         t += gridDim.x * blockDim.x) {
        float4 mn = g_pmn4[t];
        float4 mx = g_pmx4[t];
#pragma unroll
        for (int c = 1; c < RSPLIT; c++) {
            float4 a = g_pmn4[c * PP4 + t];
            float4 b = g_pmx4[c * PP4 + t];
            mn.x = fminf(mn.x, a.x); mx.x = fmaxf(mx.x, b.x);
            mn.y = fminf(mn.y, a.y); mx.y = fmaxf(mx.y, b.y);
            mn.z = fminf(mn.z, a.z); mx.z = fmaxf(mx.z, b.z);
            mn.w = fminf(mn.w, a.w); mx.w = fmaxf(mx.w, b.w);
        }
        float mnk[4] = {mn.x, mn.y, mn.z, mn.w};
        float mxk[4] = {mx.x, mx.y, mx.z, mx.w};
        int p0 = 4 * t;
#pragma unroll
        for (int j = 0; j < 4; j++) {
            int p = p0 + j;
#pragma unroll
            for (int k = 0; k < NCAND; k++) {
                int   L   = LENS[k];            // literal after unroll
                float ctr = s_pat[p % L];
                float d   = fmaxf(mxk[j] - ctr, ctr - mnk[j]);
                acc[k]    = fmaxf(acc[k], d);
            }
        }
    }

#pragma unroll
    for (int k = 0; k < NCAND; k++)
        atomicMax(&s_max[k], __float_as_uint(acc[k]));
    __syncthreads();
    if (threadIdx.x < NCAND)
        atomicMax(&g_md[threadIdx.x], s_max[threadIdx.x]);
}

// ---------------------------------------------------------------------------
// Stage 3: scores + first-max argmax, 42 fp32 outputs:
//   [0:20)  max_diffs, [20:40) eff_scores, [40] best_idx, [41] best_score
// ---------------------------------------------------------------------------
__global__ void pm_stage3(float* __restrict__ out, int out_size) {
    if (threadIdx.x != 0 || blockIdx.x != 0) return;
    const int LENS[NCAND] = {4,5,6,7,8,9,10,11,12,14,15,16,18,20,21,22,24,28,30,32};
    float best = 0.0f;
    int   bidx = 0;
#pragma unroll
    for (int k = 0; k < NCAND; k++) {
        float md  = __uint_as_float(g_md[k]);
        int   L   = LENS[k];
        float raw = (float)((double)(NTOT / L) / (double)L);
        float eff = (md < 0.01f) ? raw : 0.0f;
        if (k < out_size)          out[k]      = md;
        if (20 + k < out_size)     out[20 + k] = eff;
        if (eff > best) { best = eff; bidx = k; }   // first max, like jnp.argmax
    }
    if (out_size > 40) out[40] = (float)bidx;
    if (out_size > 41) out[41] = best;
}

// ---------------------------------------------------------------------------
extern "C" void kernel_launch(void* const* d_in, const int* in_sizes, int n_in,
                              void* d_out, int out_size) {
    const float* x = (const float*)d_in[0];
    float* out = (float*)d_out;

    pm_init<<<1, 32>>>();

    dim3 g1((PP4 + 255) / 256, RSPLIT);
    pm_stage1<<<g1, 256>>>((const float4*)x);

    pm_stage2<<<110, 256>>>(x);

    pm_stage3<<<1, 32>>>(out, out_size);
}

// round 2
// speedup vs baseline: 1.0063x; 1.0063x over previous
#include <cuda_runtime.h>
#include <cuda_bf16.h>

// Problem constants (fixed by the dataset):
//   N = 55440*1024 = 56,770,560 fp32 elements
//   Candidate lengths: L in [4,32], N % L == 0  -> 20 candidates
//   P = lcm(candidates) = 110880, N / P = 512
#define NTOT   56770560
#define PP     110880
#define PP4    27720        // PP / 4 (float4 positions)
#define RSPLIT 4            // split the 512 repeats 4 ways for occupancy
#define RCHUNK 128          // 512 / RSPLIT
#define NCAND  20

// Scratch (allocation-free rule: __device__ globals)
__device__ float4   g_pmn4[RSPLIT * PP4];   // partial per-position min
__device__ float4   g_pmx4[RSPLIT * PP4];   // partial per-position max
__device__ unsigned g_md[NCAND];            // float-bit max per candidate
__device__ unsigned g_done;                 // stage2 block-completion counter (returns to 0)

// ---------------------------------------------------------------------------
// Stage 1: per-period-position min/max over one r-chunk of 128 repeats.
// Thread t (of PP4) handles 4 consecutive positions via float4; blockIdx.y
// selects the r-chunk. Warp loads are 512B contiguous -> fully coalesced.
// Block (0,0) additionally zeroes the stage-2 atomicMax targets (diffs >= 0
// and bits(0.0f)==0, so uint ordering == float ordering).
// ---------------------------------------------------------------------------
__global__ __launch_bounds__(256) void pm_stage1(const float4* __restrict__ x4) {
    if (blockIdx.x == 0 && blockIdx.y == 0 && threadIdx.x < NCAND)
        g_md[threadIdx.x] = 0u;     // visible to stage2 via inter-kernel ordering

    int t = blockIdx.x * blockDim.x + threadIdx.x;
    if (t >= PP4) return;
    int c = blockIdx.y;

    int base = c * (RCHUNK * PP4) + t;
    float4 v = x4[base];
    float4 mn = v, mx = v;

#pragma unroll 8
    for (int r = 1; r < RCHUNK; r++) {
        float4 u = x4[base + r * PP4];
        mn.x = fminf(mn.x, u.x); mx.x = fmaxf(mx.x, u.x);
        mn.y = fminf(mn.y, u.y); mx.y = fmaxf(mx.y, u.y);
        mn.z = fminf(mn.z, u.z); mx.z = fmaxf(mx.z, u.z);
        mn.w = fminf(mn.w, u.w); mx.w = fmaxf(mx.w, u.w);
    }
    g_pmn4[c * PP4 + t] = mn;
    g_pmx4[c * PP4 + t] = mx;
}

// ---------------------------------------------------------------------------
// Stage 2 (+ fused finalize): combine the 4 partials and, for every period
// position p, fold max(mx[p]-pat, pat-mn[p]) into the per-L accumulators.
// pat = x[p % L] with compile-time-constant modulus (unrolled).
// Exactness: max over a set of |fl(v-c)| is attained at an extreme of v, and
// fl(v-c) is monotone in v and sign-symmetric, so max(fl(mx-c), fl(c-mn)).
// The last block to finish computes scores/argmax and writes the output
// (fenced last-block-done pattern; counter resets to 0 for graph replay).
// ---------------------------------------------------------------------------
__global__ __launch_bounds__(256) void pm_stage2(const float* __restrict__ x,
                                                 float* __restrict__ out,
                                                 int out_size) {
    __shared__ float    s_pat[32];
    __shared__ unsigned s_max[NCAND];
    __shared__ bool     s_last;
    if (threadIdx.x < 32)     s_pat[threadIdx.x] = x[threadIdx.x];
    if (threadIdx.x < NCAND)  s_max[threadIdx.x] = 0u;
    __syncthreads();

    const int LENS[NCAND] = {4,5,6,7,8,9,10,11,12,14,15,16,18,20,21,22,24,28,30,32};

    float acc[NCAND];
#pragma unroll
    for (int k = 0; k < NCAND; k++) acc[k] = 0.0f;

    for (int t = blockIdx.x * blockDim.x + threadIdx.x; t < PP4;
         t += gridDim.x * blockDim.x) {
        float4 mn = g_pmn4[t];
        float4 mx = g_pmx4[t];
#pragma unroll
        for (int c = 1; c < RSPLIT; c++) {
            float4 a = g_pmn4[c * PP4 + t];
            float4 b = g_pmx4[c * PP4 + t];
            mn.x = fminf(mn.x, a.x); mx.x = fmaxf(mx.x, b.x);
            mn.y = fminf(mn.y, a.y); mx.y = fmaxf(mx.y, b.y);
            mn.z = fminf(mn.z, a.z); mx.z = fmaxf(mx.z, b.z);
            mn.w = fminf(mn.w, a.w); mx.w = fmaxf(mx.w, b.w);
        }
        float mnk[4] = {mn.x, mn.y, mn.z, mn.w};
        float mxk[4] = {mx.x, mx.y, mx.z, mx.w};
        int p0 = 4 * t;
#pragma unroll
        for (int j = 0; j < 4; j++) {
            int p = p0 + j;
#pragma unroll
            for (int k = 0; k < NCAND; k++) {
                int   L   = LENS[k];            // literal after unroll
                float ctr = s_pat[p % L];
                float d   = fmaxf(mxk[j] - ctr, ctr - mnk[j]);
                acc[k]    = fmaxf(acc[k], d);
            }
        }
    }

#pragma unroll
    for (int k = 0; k < NCAND; k++)
        atomicMax(&s_max[k], __float_as_uint(acc[k]));
    __syncthreads();
    if (threadIdx.x < NCAND)
        atomicMax(&g_md[threadIdx.x], s_max[threadIdx.x]);

    // ---- fused finalize: last block to complete writes the 42 outputs ----
    __threadfence();                       // make g_md atomics globally visible
    if (threadIdx.x == 0) {
        unsigned prev = atomicAdd(&g_done, 1u);
        s_last = (prev == gridDim.x - 1);
    }
    __syncthreads();
    if (!s_last) return;

    if (threadIdx.x == 0) {
        g_done = 0u;                       // reset for next graph replay
        float best = 0.0f;
        int   bidx = 0;
#pragma unroll
        for (int k = 0; k < NCAND; k++) {
            float md  = __uint_as_float(g_md[k]);
            int   L   = LENS[k];
            float raw = (float)((double)(NTOT / L) / (double)L);
            float eff = (md < 0.01f) ? raw : 0.0f;
            if (k < out_size)          out[k]      = md;
            if (20 + k < out_size)     out[20 + k] = eff;
            if (eff > best) { best = eff; bidx = k; }   // first max, like jnp.argmax
        }
        if (out_size > 40) out[40] = (float)bidx;
        if (out_size > 41) out[41] = best;
    }
}

// ---------------------------------------------------------------------------
extern "C" void kernel_launch(void* const* d_in, const int* in_sizes, int n_in,
                              void* d_out, int out_size) {
    const float* x = (const float*)d_in[0];
    float* out = (float*)d_out;

    dim3 g1((PP4 + 255) / 256, RSPLIT);
    pm_stage1<<<g1, 256>>>((const float4*)x);

    pm_stage2<<<110, 256>>>(x, out, out_size);
}

// round 3
// speedup vs baseline: 1.0534x; 1.0468x over previous
#include <cuda_runtime.h>
#include <cuda_bf16.h>

// Problem constants (fixed by the dataset):
//   N = 55440*1024 = 56,770,560 fp32; candidates L in [4,32] dividing N -> 20
//   P = lcm(candidates) = 110880, N / P = 512
#define NTOT   56770560
#define PP4    27720        // P/4 float4 positions per period
#define RSPLIT 4            // split the 512 repeats 4 ways for occupancy
#define RCHUNK 128          // 512 / RSPLIT
#define NCAND  20
#define NBX    109          // ceil(PP4 / 256)
#define NBLK   (NBX * RSPLIT)   // 436 blocks, single wave at 3 blocks/SM

// Scratch (__device__ globals; plain per-block stores -> no init required)
__device__ unsigned g_blk[NBLK][NCAND];  // per-block candidate maxima (float bits)
__device__ unsigned g_done;             // completion counter, self-resets to 0

// ---------------------------------------------------------------------------
// Single fused kernel.
// Phase A: thread t (float4 position), chunk c=blockIdx.y: streaming min/max
//          over 128 repeats (coalesced 512B warp loads, read-once -> __ldcs).
// Phase B: evaluate all 20 candidates on the chunk-local (mn, mx). Valid since
//          max over (p, r) = max over chunks of the per-chunk candidate max,
//          and max_v |fl(v-c)| = max(fl(mx-c), fl(c-mn)) exactly (fl monotone,
//          sign-symmetric). pat = x[p % L], L a literal after unroll.
// Phase C: shfl-butterfly warp reduce -> lane-0 shared atomics -> per-block
//          plain store to g_blk. Last block reduces g_blk, computes scores,
//          argmax, writes 42 outputs. Counter resets for graph replay.
// ---------------------------------------------------------------------------
__global__ __launch_bounds__(256, 3) void pm_fused(const float4* __restrict__ x4,
                                                   float* __restrict__ out,
                                                   int out_size) {
    __shared__ float    s_pat[32];
    __shared__ unsigned s_max[NCAND];
    __shared__ bool     s_last;
    if (threadIdx.x < 32)    s_pat[threadIdx.x] = ((const float*)x4)[threadIdx.x];
    if (threadIdx.x < NCAND) s_max[threadIdx.x] = 0u;
    __syncthreads();

    const int LENS[NCAND] = {4,5,6,7,8,9,10,11,12,14,15,16,18,20,21,22,24,28,30,32};

    float acc[NCAND];
#pragma unroll
    for (int k = 0; k < NCAND; k++) acc[k] = 0.0f;

    int t = blockIdx.x * 256 + threadIdx.x;
    if (t < PP4) {
        // --- Phase A: chunk-local min/max ---
        const float4* p = x4 + (size_t)blockIdx.y * (RCHUNK * PP4) + t;
        float4 v = __ldcs(p);
        float4 mn = v, mx = v;
#pragma unroll 8
        for (int r = 1; r < RCHUNK; r++) {
            float4 u = __ldcs(p + r * PP4);
            mn.x = fminf(mn.x, u.x); mx.x = fmaxf(mx.x, u.x);
            mn.y = fminf(mn.y, u.y); mx.y = fmaxf(mx.y, u.y);
            mn.z = fminf(mn.z, u.z); mx.z = fmaxf(mx.z, u.z);
            mn.w = fminf(mn.w, u.w); mx.w = fmaxf(mx.w, u.w);
        }

        // --- Phase B: 20-candidate fold on this thread's 4 positions ---
        float mnk[4] = {mn.x, mn.y, mn.z, mn.w};
        float mxk[4] = {mx.x, mx.y, mx.z, mx.w};
        int p0 = 4 * t;
#pragma unroll
        for (int j = 0; j < 4; j++) {
            int pp = p0 + j;
#pragma unroll
            for (int k = 0; k < NCAND; k++) {
                int   L   = LENS[k];                 // literal after unroll
                float ctr = s_pat[pp % L];
                float d   = fmaxf(mxk[j] - ctr, ctr - mnk[j]);
                acc[k]    = fmaxf(acc[k], d);
            }
        }
    }

    // --- Phase C: warp shfl reduce, lane-0 shared atomics, per-block store ---
#pragma unroll
    for (int k = 0; k < NCAND; k++) {
        float a = acc[k];
        a = fmaxf(a, __shfl_xor_sync(0xFFFFFFFFu, a, 16));
        a = fmaxf(a, __shfl_xor_sync(0xFFFFFFFFu, a, 8));
        a = fmaxf(a, __shfl_xor_sync(0xFFFFFFFFu, a, 4));
        a = fmaxf(a, __shfl_xor_sync(0xFFFFFFFFu, a, 2));
        a = fmaxf(a, __shfl_xor_sync(0xFFFFFFFFu, a, 1));
        acc[k] = a;
    }
    if ((threadIdx.x & 31) == 0) {
#pragma unroll
        for (int k = 0; k < NCAND; k++)
            atomicMax(&s_max[k], __float_as_uint(acc[k]));
    }
    __syncthreads();

    int bid = blockIdx.y * gridDim.x + blockIdx.x;
    if (threadIdx.x < NCAND)
        g_blk[bid][threadIdx.x] = s_max[threadIdx.x];

    __threadfence();   // publish g_blk before signaling completion
    if (threadIdx.x == 0) {
        unsigned prev = atomicAdd(&g_done, 1u);
        s_last = (prev == NBLK - 1);
    }
    __syncthreads();
    if (!s_last) return;

    // --- Finalize (one block): reduce g_blk, scores, argmax, outputs ---
    __threadfence();   // acquire all writers' g_blk stores
    __shared__ unsigned s_fin[NCAND];
    if (threadIdx.x == 0) g_done = 0u;            // reset for next replay
    if (threadIdx.x < NCAND) s_fin[threadIdx.x] = 0u;
    __syncthreads();

    if (threadIdx.x < 240) {                      // 12 groups x 20 candidates
        int g = threadIdx.x / NCAND;
        int k = threadIdx.x % NCAND;
        unsigned v = 0u;
        for (int b = g; b < NBLK; b += 12)
            v = max(v, g_blk[b][k]);
        atomicMax(&s_fin[k], v);
    }
    __syncthreads();

    if (threadIdx.x == 0) {
        float best = 0.0f;
        int   bidx = 0;
#pragma unroll
        for (int k = 0; k < NCAND; k++) {
            float md  = __uint_as_float(s_fin[k]);
            int   L   = LENS[k];
            float raw = (float)((double)(NTOT / L) / (double)L);
            float eff = (md < 0.01f) ? raw : 0.0f;
            if (k < out_size)      out[k]      = md;
            if (20 + k < out_size) out[20 + k] = eff;
            if (eff > best) { best = eff; bidx = k; }  // first max, like jnp.argmax
        }
        if (out_size > 40) out[40] = (float)bidx;
        if (out_size > 41) out[41] = best;
    }
}

// ---------------------------------------------------------------------------
extern "C" void kernel_launch(void* const* d_in, const int* in_sizes, int n_in,
                              void* d_out, int out_size) {
    const float* x = (const float*)d_in[0];
    float* out = (float*)d_out;

    dim3 grid(NBX, RSPLIT);
    pm_fused<<<grid, 256>>>((const float4*)x, out, out_size);
}